// round 2
// baseline (speedup 1.0000x reference)
#include <cuda_runtime.h>
#include <math.h>

#define NTOK 2048
#define DIMV 1024
#define NEXP 8
#define HDIM 2048

// ---------------- scratch (__device__ globals: no allocation allowed) ----------------
__device__ int   g_counts[NEXP];
__device__ int   g_offsets[NEXP];
__device__ int   g_perm[NEXP * NTOK];    // token id per (expert, local slot)
__device__ float g_pw[NEXP * NTOK];      // normalized combine weight per slot
__device__ float g_h[(size_t)2 * NTOK * HDIM];   // 4096 x 2048 fp32 = 32 MB

// ---------------- 0) zero output + counters ----------------
__global__ void zero_kernel(float* __restrict__ out) {
    int i = blockIdx.x * blockDim.x + threadIdx.x;
    if (i < NTOK * DIMV) out[i] = 0.f;
    if (i < NEXP) g_counts[i] = 0;
}

// ---------------- 1) gating: logits -> sigmoid -> top2 -> permutation ----------------
__global__ void gate_kernel(const float* __restrict__ x,
                            const float* __restrict__ gw,
                            const float* __restrict__ bias) {
    int t = blockIdx.x;
    const float* xr = x + (size_t)t * DIMV;

    float acc[NEXP];
#pragma unroll
    for (int e = 0; e < NEXP; e++) acc[e] = 0.f;

    for (int d = threadIdx.x; d < DIMV; d += blockDim.x) {
        float xv = xr[d];
#pragma unroll
        for (int e = 0; e < NEXP; e++) acc[e] += xv * gw[e * DIMV + d];
    }

    __shared__ float sred[256][NEXP + 1];
#pragma unroll
    for (int e = 0; e < NEXP; e++) sred[threadIdx.x][e] = acc[e];
    __syncthreads();
    for (int s = 128; s > 0; s >>= 1) {
        if (threadIdx.x < s) {
#pragma unroll
            for (int e = 0; e < NEXP; e++)
                sred[threadIdx.x][e] += sred[threadIdx.x + s][e];
        }
        __syncthreads();
    }

    if (threadIdx.x == 0) {
        float sc[NEXP];
#pragma unroll
        for (int e = 0; e < NEXP; e++)
            sc[e] = 1.f / (1.f + __expf(-(sred[0][e] + bias[e])));

        // top-2, strict > so ties keep the lowest index (matches jax.lax.top_k)
        int i0 = 0;
#pragma unroll
        for (int e = 1; e < NEXP; e++) if (sc[e] > sc[i0]) i0 = e;
        int i1 = (i0 == 0) ? 1 : 0;
#pragma unroll
        for (int e = 0; e < NEXP; e++)
            if (e != i0 && sc[e] > sc[i1]) i1 = e;

        float s0 = sc[i0], s1 = sc[i1];
        float inv = 1.f / (s0 + s1 + 1e-6f);

        int slot0 = atomicAdd(&g_counts[i0], 1);
        g_perm[i0 * NTOK + slot0] = t;
        g_pw[i0 * NTOK + slot0]   = s0 * inv;
        int slot1 = atomicAdd(&g_counts[i1], 1);
        g_perm[i1 * NTOK + slot1] = t;
        g_pw[i1 * NTOK + slot1]   = s1 * inv;
    }
}

// ---------------- 2) exclusive scan of expert counts ----------------
__global__ void offsets_kernel() {
    if (threadIdx.x == 0) {
        int s = 0;
        for (int e = 0; e < NEXP; e++) { g_offsets[e] = s; s += g_counts[e]; }
    }
}

// ---------------- 3) GEMM1: h = silu(x_gathered @ w1[e]^T) ----------------
// A: gathered x rows [cnt, 1024] (K-contig), B: w1[e] [2048, 1024] (K-contig)
// tile 64x64x16, 256 threads, 4x4 microtile
__global__ void __launch_bounds__(256) gemm1_kernel(const float* __restrict__ x,
                                                    const float* __restrict__ w1) {
    int e   = blockIdx.z;
    int cnt = g_counts[e];
    int m0  = blockIdx.y * 64;
    if (m0 >= cnt) return;
    int n0  = blockIdx.x * 64;
    int off = g_offsets[e];
    const float* B = w1 + (size_t)e * HDIM * DIMV;

    __shared__ float As[16][68];
    __shared__ float Bs[16][68];

    int tid = threadIdx.x;
    int lr  = tid & 63;   // tile row for loads
    int lk  = tid >> 6;   // 0..3 -> which float4 along K

    int arow = m0 + lr;
    int tokA = (arow < cnt) ? g_perm[e * NTOK + arow] : -1;
    const float4* aptr = (tokA >= 0)
        ? reinterpret_cast<const float4*>(x + (size_t)tokA * DIMV) : nullptr;
    const float4* bptr = reinterpret_cast<const float4*>(B + (size_t)(n0 + lr) * DIMV);

    float acc[4][4];
#pragma unroll
    for (int i = 0; i < 4; i++)
#pragma unroll
        for (int j = 0; j < 4; j++) acc[i][j] = 0.f;

    int rm = (tid & 15) * 4;
    int rn = (tid >> 4) * 4;

    for (int k0 = 0; k0 < DIMV; k0 += 16) {
        float4 av = make_float4(0.f, 0.f, 0.f, 0.f);
        if (aptr) av = aptr[(k0 >> 2) + lk];
        float4 bv = bptr[(k0 >> 2) + lk];
        As[lk * 4 + 0][lr] = av.x;
        As[lk * 4 + 1][lr] = av.y;
        As[lk * 4 + 2][lr] = av.z;
        As[lk * 4 + 3][lr] = av.w;
        Bs[lk * 4 + 0][lr] = bv.x;
        Bs[lk * 4 + 1][lr] = bv.y;
        Bs[lk * 4 + 2][lr] = bv.z;
        Bs[lk * 4 + 3][lr] = bv.w;
        __syncthreads();
#pragma unroll
        for (int k = 0; k < 16; k++) {
            float a[4], b[4];
#pragma unroll
            for (int i = 0; i < 4; i++) a[i] = As[k][rm + i];
#pragma unroll
            for (int j = 0; j < 4; j++) b[j] = Bs[k][rn + j];
#pragma unroll
            for (int i = 0; i < 4; i++)
#pragma unroll
                for (int j = 0; j < 4; j++) acc[i][j] = fmaf(a[i], b[j], acc[i][j]);
        }
        __syncthreads();
    }

#pragma unroll
    for (int i = 0; i < 4; i++) {
        int r = m0 + rm + i;
        if (r < cnt) {
            float* hrow = g_h + (size_t)(off + r) * HDIM + n0 + rn;
#pragma unroll
            for (int j = 0; j < 4; j++) {
                float v = acc[i][j];
                hrow[j] = v / (1.f + __expf(-v));   // silu
            }
        }
    }
}

// ---------------- 4) GEMM2: out[tok] += w * (h @ w2[e]^T) ----------------
// A: g_h rows [cnt, 2048] (K-contig), B: w2[e] [1024, 2048] (K-contig)
__global__ void __launch_bounds__(256) gemm2_kernel(const float* __restrict__ w2,
                                                    float* __restrict__ out) {
    int e   = blockIdx.z;
    int cnt = g_counts[e];
    int m0  = blockIdx.y * 64;
    if (m0 >= cnt) return;
    int n0  = blockIdx.x * 64;
    int off = g_offsets[e];
    const float* B = w2 + (size_t)e * DIMV * HDIM;

    __shared__ float As[16][68];
    __shared__ float Bs[16][68];

    int tid = threadIdx.x;
    int lr  = tid & 63;
    int lk  = tid >> 6;

    int arow = m0 + lr;
    const float4* aptr = (arow < cnt)
        ? reinterpret_cast<const float4*>(g_h + (size_t)(off + arow) * HDIM) : nullptr;
    const float4* bptr = reinterpret_cast<const float4*>(B + (size_t)(n0 + lr) * HDIM);

    float acc[4][4];
#pragma unroll
    for (int i = 0; i < 4; i++)
#pragma unroll
        for (int j = 0; j < 4; j++) acc[i][j] = 0.f;

    int rm = (tid & 15) * 4;
    int rn = (tid >> 4) * 4;

    for (int k0 = 0; k0 < HDIM; k0 += 16) {
        float4 av = make_float4(0.f, 0.f, 0.f, 0.f);
        if (aptr) av = aptr[(k0 >> 2) + lk];
        float4 bv = bptr[(k0 >> 2) + lk];
        As[lk * 4 + 0][lr] = av.x;
        As[lk * 4 + 1][lr] = av.y;
        As[lk * 4 + 2][lr] = av.z;
        As[lk * 4 + 3][lr] = av.w;
        Bs[lk * 4 + 0][lr] = bv.x;
        Bs[lk * 4 + 1][lr] = bv.y;
        Bs[lk * 4 + 2][lr] = bv.z;
        Bs[lk * 4 + 3][lr] = bv.w;
        __syncthreads();
#pragma unroll
        for (int k = 0; k < 16; k++) {
            float a[4], b[4];
#pragma unroll
            for (int i = 0; i < 4; i++) a[i] = As[k][rm + i];
#pragma unroll
            for (int j = 0; j < 4; j++) b[j] = Bs[k][rn + j];
#pragma unroll
            for (int i = 0; i < 4; i++)
#pragma unroll
                for (int j = 0; j < 4; j++) acc[i][j] = fmaf(a[i], b[j], acc[i][j]);
        }
        __syncthreads();
    }

#pragma unroll
    for (int i = 0; i < 4; i++) {
        int r = m0 + rm + i;
        if (r < cnt) {
            int   tok = g_perm[e * NTOK + r];
            float w   = g_pw[e * NTOK + r];
            float* orow = out + (size_t)tok * DIMV + n0 + rn;
#pragma unroll
            for (int j = 0; j < 4; j++) atomicAdd(&orow[j], w * acc[i][j]);
        }
    }
}

// ---------------- launch ----------------
extern "C" void kernel_launch(void* const* d_in, const int* in_sizes, int n_in,
                              void* d_out, int out_size) {
    const float* x      = (const float*)d_in[0];   // [1,2048,1024]
    const float* gate_w = (const float*)d_in[1];   // [8,1024]
    const float* bias   = (const float*)d_in[2];   // [8]
    const float* w1     = (const float*)d_in[3];   // [8,2048,1024]
    const float* w2     = (const float*)d_in[4];   // [8,1024,2048]
    float* out          = (float*)d_out;           // [1,2048,1024]

    zero_kernel<<<(NTOK * DIMV + 255) / 256, 256>>>(out);
    gate_kernel<<<NTOK, 256>>>(x, gate_w, bias);
    offsets_kernel<<<1, 32>>>();
    gemm1_kernel<<<dim3(HDIM / 64, NTOK / 64, NEXP), 256>>>(x, w1);
    gemm2_kernel<<<dim3(DIMV / 64, NTOK / 64, NEXP), 256>>>(w2, out);
}

// round 4
// speedup vs baseline: 4.7134x; 4.7134x over previous
#include <cuda_runtime.h>
#include <cuda_fp16.h>
#include <math.h>
#include <stdint.h>

#define NTOK 2048
#define DIMV 1024
#define NEXP 8
#define HDIM 2048

#define MT 128
#define NT 128
#define BK 64              // halves per K chunk = 128 bytes per row (SW128)

// smem: A0 | A1 | B0 | B1, each 128 rows * 128B = 16 KB
#define SA0 0
#define SB0 32768
#define SMEM_BYTES 65536

// ---------------- scratch ----------------
__device__ int   g_counts[NEXP];
__device__ int   g_offsets[NEXP];
__device__ int   g_perm[NEXP * NTOK];
__device__ int   g_te[NTOK * 2];
__device__ int   g_tl[NTOK * 2];
__device__ float g_tw[NTOK * 2];
__device__ __align__(16) __half g_xh[NTOK * DIMV];
__device__ __align__(16) __half g_w1h[(size_t)NEXP * HDIM * DIMV];
__device__ __align__(16) __half g_w2h[(size_t)NEXP * DIMV * HDIM];
__device__ __align__(16) __half g_hh[(size_t)2 * NTOK * HDIM];
__device__ __align__(16) float  g_y[(size_t)2 * NTOK * DIMV];

// ---------------- PTX helpers ----------------
__device__ __forceinline__ uint32_t smem_u32(const void* p) {
    uint32_t a;
    asm("{ .reg .u64 t; cvta.to.shared.u64 t, %1; cvt.u32.u64 %0, t; }" : "=r"(a) : "l"(p));
    return a;
}
#define CPASYNC16(dst, src, sz) \
    asm volatile("cp.async.cg.shared.global [%0], [%1], 16, %2;" :: "r"(dst), "l"(src), "r"(sz) : "memory")
#define CPCOMMIT() asm volatile("cp.async.commit_group;" ::: "memory")

#define LDSM_X4(r0, r1, r2, r3, addr) \
    asm volatile("ldmatrix.sync.aligned.m8n8.x4.shared.b16 {%0,%1,%2,%3}, [%4];" \
        : "=r"(r0), "=r"(r1), "=r"(r2), "=r"(r3) : "r"(addr))

#define MMA16816(d, a, b0, b1) \
    asm volatile("mma.sync.aligned.m16n8k16.row.col.f32.f16.f16.f32 " \
        "{%0,%1,%2,%3},{%4,%5,%6,%7},{%8,%9},{%0,%1,%2,%3};" \
        : "+f"((d)[0]), "+f"((d)[1]), "+f"((d)[2]), "+f"((d)[3]) \
        : "r"((a)[0]), "r"((a)[1]), "r"((a)[2]), "r"((a)[3]), "r"(b0), "r"(b1))

__device__ __forceinline__ float silu(float v) { return v / (1.f + __expf(-v)); }

// ---------------- 0) zero counters ----------------
__global__ void zero_kernel() {
    if (threadIdx.x < NEXP) g_counts[threadIdx.x] = 0;
}

// ---------------- convert fp32 -> fp16 ----------------
__global__ void cvt_kernel(const float4* __restrict__ src, __half2* __restrict__ dst, int n4) {
    int i = blockIdx.x * blockDim.x + threadIdx.x;
    if (i < n4) {
        float4 v = src[i];
        dst[2 * i]     = __floats2half2_rn(v.x, v.y);
        dst[2 * i + 1] = __floats2half2_rn(v.z, v.w);
    }
}

// ---------------- 1) gating (also emits x as fp16) ----------------
__global__ void gate_kernel(const float* __restrict__ x,
                            const float* __restrict__ gw,
                            const float* __restrict__ bias) {
    int t = blockIdx.x;
    const float* xr = x + (size_t)t * DIMV;

    float acc[NEXP];
#pragma unroll
    for (int e = 0; e < NEXP; e++) acc[e] = 0.f;
    for (int d = threadIdx.x; d < DIMV; d += blockDim.x) {
        float xv = xr[d];
        g_xh[(size_t)t * DIMV + d] = __float2half_rn(xv);
#pragma unroll
        for (int e = 0; e < NEXP; e++) acc[e] += xv * gw[e * DIMV + d];
    }

    __shared__ float sred[256][NEXP + 1];
#pragma unroll
    for (int e = 0; e < NEXP; e++) sred[threadIdx.x][e] = acc[e];
    __syncthreads();
    for (int s = 128; s > 0; s >>= 1) {
        if (threadIdx.x < s) {
#pragma unroll
            for (int e = 0; e < NEXP; e++)
                sred[threadIdx.x][e] += sred[threadIdx.x + s][e];
        }
        __syncthreads();
    }

    if (threadIdx.x == 0) {
        float sc[NEXP];
#pragma unroll
        for (int e = 0; e < NEXP; e++)
            sc[e] = 1.f / (1.f + __expf(-(sred[0][e] + bias[e])));
        int i0 = 0;
#pragma unroll
        for (int e = 1; e < NEXP; e++) if (sc[e] > sc[i0]) i0 = e;
        int i1 = (i0 == 0) ? 1 : 0;
#pragma unroll
        for (int e = 0; e < NEXP; e++)
            if (e != i0 && sc[e] > sc[i1]) i1 = e;

        float s0 = sc[i0], s1 = sc[i1];
        float inv = 1.f / (s0 + s1 + 1e-6f);

        int slot0 = atomicAdd(&g_counts[i0], 1);
        g_perm[i0 * NTOK + slot0] = t;
        int slot1 = atomicAdd(&g_counts[i1], 1);
        g_perm[i1 * NTOK + slot1] = t;

        g_te[2 * t] = i0;     g_tl[2 * t] = slot0;     g_tw[2 * t] = s0 * inv;
        g_te[2 * t + 1] = i1; g_tl[2 * t + 1] = slot1; g_tw[2 * t + 1] = s1 * inv;
    }
}

// ---------------- 2) offsets ----------------
__global__ void offsets_kernel() {
    if (threadIdx.x == 0) {
        int s = 0;
        for (int e = 0; e < NEXP; e++) { g_offsets[e] = s; s += g_counts[e]; }
    }
}

// ---------------- 3) fp16 mma.sync grouped GEMM ----------------
// C[128,128] = A[128,K] @ B[128,K]^T per expert tile.
// 8 warps as 4(m) x 2(n); warp tile 32x64; m16n8k16 fragments via ldmatrix.
template <int KTOT, int NTOTAL, bool IS_G1>
__global__ void __launch_bounds__(256) gemm_mma(const __half* __restrict__ Ah,
                                                const __half* __restrict__ Wh) {
    int e = blockIdx.z;
    int cnt = g_counts[e];
    int m0 = blockIdx.y * MT;
    if (m0 >= cnt) return;
    int n0 = blockIdx.x * NT;
    int off = g_offsets[e];

    extern __shared__ char smem[];
    uint32_t sb = smem_u32(smem);
    int tid = threadIdx.x, wid = tid >> 5, lane = tid & 31;

    // ---- staging assignment: thread -> (row tid&127, half tid>>7) of A and B
    int ra = tid & 127;
    int ha = tid >> 7;
    bool avalid = (m0 + ra) < cnt;
    const __half* asrc;
    if (IS_G1) {
        int tok = avalid ? g_perm[e * NTOK + m0 + ra] : 0;
        asrc = Ah + (size_t)tok * KTOT + ha * 32;
    } else {
        asrc = Ah + (size_t)(avalid ? (off + m0 + ra) : 0) * KTOT + ha * 32;
    }
    const __half* bsrc = Wh + (size_t)e * NTOTAL * KTOT + (size_t)(n0 + ra) * KTOT + ha * 32;
    uint32_t adst0 = sb + SA0 + (uint32_t)ra * 128;
    uint32_t bdst0 = sb + SB0 + (uint32_t)ra * 128;
    uint32_t asz = avalid ? 16u : 0u;
    uint32_t rx = (uint32_t)(ra & 7);

    auto issue = [&](int kc, int buf) {
        uint32_t ab = adst0 + buf * 16384;
        const __half* as = asrc + kc * BK;
        uint32_t bb = bdst0 + buf * 16384;
        const __half* bs = bsrc + kc * BK;
#pragma unroll
        for (int j = 0; j < 4; j++) {
            uint32_t bch = (uint32_t)(ha * 4 + j);
            CPASYNC16(ab + ((bch ^ rx) << 4), as + j * 8, asz);
            CPASYNC16(bb + ((bch ^ rx) << 4), bs + j * 8, 16u);
        }
        CPCOMMIT();
    };

    // ---- fragment geometry
    int wm = wid >> 1, wn = wid & 1;
    int m_base = wm * 32, n_base = wn * 64;
    int lr8 = lane & 7, q = lane >> 3;

    int rowA[2], rowB[4];
#pragma unroll
    for (int mi = 0; mi < 2; mi++) rowA[mi] = m_base + mi * 16 + (q & 1) * 8 + lr8;
#pragma unroll
    for (int np = 0; np < 4; np++) rowB[np] = n_base + np * 16 + (q >> 1) * 8 + lr8;

    float acc[2][8][4];
#pragma unroll
    for (int mi = 0; mi < 2; mi++)
#pragma unroll
        for (int nj = 0; nj < 8; nj++)
#pragma unroll
            for (int c = 0; c < 4; c++) acc[mi][nj][c] = 0.f;

    constexpr int NC = KTOT / BK;
    issue(0, 0);

    for (int kc = 0; kc < NC; kc++) {
        int buf = kc & 1;
        if (kc + 1 < NC) {
            issue(kc + 1, buf ^ 1);
            asm volatile("cp.async.wait_group 1;" ::: "memory");
        } else {
            asm volatile("cp.async.wait_group 0;" ::: "memory");
        }
        __syncthreads();

        uint32_t Ab = sb + SA0 + buf * 16384;
        uint32_t Bb = sb + SB0 + buf * 16384;
#pragma unroll
        for (int s = 0; s < 4; s++) {
            uint32_t a[2][4];
#pragma unroll
            for (int mi = 0; mi < 2; mi++) {
                uint32_t bch = (uint32_t)(s * 2 + (q >> 1));
                uint32_t ad = Ab + (uint32_t)rowA[mi] * 128 + ((bch ^ (uint32_t)(rowA[mi] & 7)) << 4);
                LDSM_X4(a[mi][0], a[mi][1], a[mi][2], a[mi][3], ad);
            }
            uint32_t b[4][4];
#pragma unroll
            for (int np = 0; np < 4; np++) {
                uint32_t bch = (uint32_t)(s * 2 + (q & 1));
                uint32_t bd = Bb + (uint32_t)rowB[np] * 128 + ((bch ^ (uint32_t)(rowB[np] & 7)) << 4);
                LDSM_X4(b[np][0], b[np][1], b[np][2], b[np][3], bd);
            }
#pragma unroll
            for (int mi = 0; mi < 2; mi++)
#pragma unroll
                for (int np = 0; np < 4; np++) {
                    MMA16816(acc[mi][2 * np],     a[mi], b[np][0], b[np][1]);
                    MMA16816(acc[mi][2 * np + 1], a[mi], b[np][2], b[np][3]);
                }
        }
        __syncthreads();
    }

    // ---- epilogue
    int g = lane >> 2, t2 = (lane & 3) * 2;
#pragma unroll
    for (int mi = 0; mi < 2; mi++) {
        int r0 = m_base + mi * 16 + g;
        int r1 = r0 + 8;
        bool v0 = (m0 + r0) < cnt;
        bool v1 = (m0 + r1) < cnt;
        size_t gr0 = (size_t)(off + m0 + r0);
        size_t gr1 = (size_t)(off + m0 + r1);
#pragma unroll
        for (int nj = 0; nj < 8; nj++) {
            int col = n0 + n_base + nj * 8 + t2;
            if (IS_G1) {
                if (v0)
                    *(__half2*)(g_hh + gr0 * NTOTAL + col) =
                        __floats2half2_rn(silu(acc[mi][nj][0]), silu(acc[mi][nj][1]));
                if (v1)
                    *(__half2*)(g_hh + gr1 * NTOTAL + col) =
                        __floats2half2_rn(silu(acc[mi][nj][2]), silu(acc[mi][nj][3]));
            } else {
                if (v0)
                    *(float2*)(g_y + gr0 * NTOTAL + col) =
                        make_float2(acc[mi][nj][0], acc[mi][nj][1]);
                if (v1)
                    *(float2*)(g_y + gr1 * NTOTAL + col) =
                        make_float2(acc[mi][nj][2], acc[mi][nj][3]);
            }
        }
    }
}

// ---------------- 4) combine ----------------
__global__ void combine_kernel(float* __restrict__ out) {
    int i = blockIdx.x * blockDim.x + threadIdx.x;   // over NTOK*256 float4s
    int t = i >> 8;
    int c = i & 255;
    int s0 = g_offsets[g_te[2 * t]] + g_tl[2 * t];
    int s1 = g_offsets[g_te[2 * t + 1]] + g_tl[2 * t + 1];
    float w0 = g_tw[2 * t], w1 = g_tw[2 * t + 1];
    const float4* y = (const float4*)g_y;
    float4 a = y[(size_t)s0 * 256 + c];
    float4 b = y[(size_t)s1 * 256 + c];
    float4 o;
    o.x = w0 * a.x + w1 * b.x;
    o.y = w0 * a.y + w1 * b.y;
    o.z = w0 * a.z + w1 * b.z;
    o.w = w0 * a.w + w1 * b.w;
    ((float4*)out)[i] = o;
}

// ---------------- launch ----------------
extern "C" void kernel_launch(void* const* d_in, const int* in_sizes, int n_in,
                              void* d_out, int out_size) {
    const float* x      = (const float*)d_in[0];
    const float* gate_w = (const float*)d_in[1];
    const float* bias   = (const float*)d_in[2];
    const float* w1     = (const float*)d_in[3];
    const float* w2     = (const float*)d_in[4];
    float* out          = (float*)d_out;

    cudaFuncSetAttribute(gemm_mma<DIMV, HDIM, true>,
                         cudaFuncAttributeMaxDynamicSharedMemorySize, SMEM_BYTES);
    cudaFuncSetAttribute(gemm_mma<HDIM, DIMV, false>,
                         cudaFuncAttributeMaxDynamicSharedMemorySize, SMEM_BYTES);

    zero_kernel<<<1, 32>>>();

    int n4w = (NEXP * HDIM * DIMV) / 4;   // 4,194,304
    __half* w1h; cudaGetSymbolAddress((void**)&w1h, g_w1h);
    __half* w2h; cudaGetSymbolAddress((void**)&w2h, g_w2h);
    cvt_kernel<<<n4w / 256, 256>>>((const float4*)w1, (__half2*)w1h, n4w);
    cvt_kernel<<<n4w / 256, 256>>>((const float4*)w2, (__half2*)w2h, n4w);

    gate_kernel<<<NTOK, 256>>>(x, gate_w, bias);
    offsets_kernel<<<1, 32>>>();

    __half* xh; cudaGetSymbolAddress((void**)&xh, g_xh);
    __half* hh; cudaGetSymbolAddress((void**)&hh, g_hh);

    gemm_mma<DIMV, HDIM, true><<<dim3(HDIM / NT, NTOK / MT, NEXP), 256, SMEM_BYTES>>>(xh, w1h);
    gemm_mma<HDIM, DIMV, false><<<dim3(DIMV / NT, NTOK / MT, NEXP), 256, SMEM_BYTES>>>(hh, w2h);

    combine_kernel<<<(NTOK * 256) / 256, 256>>>(out);
}

// round 5
// speedup vs baseline: 5.3723x; 1.1398x over previous
#include <cuda_runtime.h>
#include <cuda_fp16.h>
#include <math.h>
#include <stdint.h>

#define NTOK 2048
#define DIMV 1024
#define NEXP 8
#define HDIM 2048

#define MT 128
#define NT 256
#define BK 64              // halves per K chunk = 128 bytes per row

// smem: 3 stages of (A: 128*128B = 16KB) + (B: 256*128B = 32KB)
#define SA_ST 16384
#define SB_BASE 49152
#define SB_ST 32768
#define SMEM_BYTES (SB_BASE + 3 * SB_ST)   // 147456

// ---------------- scratch ----------------
__device__ int   g_counts[NEXP];
__device__ int   g_offsets[NEXP];
__device__ int   g_perm[NEXP * NTOK];
__device__ int   g_te[NTOK * 2];
__device__ int   g_tl[NTOK * 2];
__device__ float g_tw[NTOK * 2];
__device__ __align__(16) __half g_xh[NTOK * DIMV];
__device__ __align__(16) __half g_w1h[(size_t)NEXP * HDIM * DIMV];
__device__ __align__(16) __half g_w2h[(size_t)NEXP * DIMV * HDIM];
__device__ __align__(16) __half g_hh[(size_t)2 * NTOK * HDIM];
__device__ __align__(16) float  g_y[(size_t)2 * NTOK * DIMV];

// ---------------- PTX helpers ----------------
__device__ __forceinline__ uint32_t smem_u32(const void* p) {
    uint32_t a;
    asm("{ .reg .u64 t; cvta.to.shared.u64 t, %1; cvt.u32.u64 %0, t; }" : "=r"(a) : "l"(p));
    return a;
}
#define CPASYNC16(dst, src, sz) \
    asm volatile("cp.async.cg.shared.global [%0], [%1], 16, %2;" :: "r"(dst), "l"(src), "r"(sz) : "memory")
#define CPCOMMIT() asm volatile("cp.async.commit_group;" ::: "memory")

#define LDSM_X4(r0, r1, r2, r3, addr) \
    asm volatile("ldmatrix.sync.aligned.m8n8.x4.shared.b16 {%0,%1,%2,%3}, [%4];" \
        : "=r"(r0), "=r"(r1), "=r"(r2), "=r"(r3) : "r"(addr))

#define MMA16816(d, a, b0, b1) \
    asm volatile("mma.sync.aligned.m16n8k16.row.col.f32.f16.f16.f32 " \
        "{%0,%1,%2,%3},{%4,%5,%6,%7},{%8,%9},{%0,%1,%2,%3};" \
        : "+f"((d)[0]), "+f"((d)[1]), "+f"((d)[2]), "+f"((d)[3]) \
        : "r"((a)[0]), "r"((a)[1]), "r"((a)[2]), "r"((a)[3]), "r"(b0), "r"(b1))

__device__ __forceinline__ float silu(float v) { return v / (1.f + __expf(-v)); }

// ---------------- 0) zero counters ----------------
__global__ void zero_kernel() {
    if (threadIdx.x < NEXP) g_counts[threadIdx.x] = 0;
}

// ---------------- convert fp32 -> fp16 ----------------
__global__ void cvt_kernel(const float4* __restrict__ src, __half2* __restrict__ dst, int n4) {
    int i = blockIdx.x * blockDim.x + threadIdx.x;
    if (i < n4) {
        float4 v = src[i];
        dst[2 * i]     = __floats2half2_rn(v.x, v.y);
        dst[2 * i + 1] = __floats2half2_rn(v.z, v.w);
    }
}

// ---------------- 1) gating: warp per token, shuffle reduce ----------------
__global__ void __launch_bounds__(256) gate_kernel(const float* __restrict__ x,
                                                   const float* __restrict__ gw,
                                                   const float* __restrict__ bias) {
    __shared__ float4 sgw[NEXP * 256];   // 8 x 1024 floats
    __shared__ float sbias[NEXP];
    int tid = threadIdx.x, wid = tid >> 5, lane = tid & 31;

    for (int i = tid; i < NEXP * 256; i += 256) sgw[i] = ((const float4*)gw)[i];
    if (tid < NEXP) sbias[tid] = bias[tid];
    __syncthreads();

    int t = blockIdx.x * 8 + wid;
    const float4* xr = (const float4*)(x + (size_t)t * DIMV);

    float4 xv[8];
#pragma unroll
    for (int i = 0; i < 8; i++) xv[i] = xr[lane + 32 * i];

    // emit fp16 x
    __half* xh = g_xh + (size_t)t * DIMV;
#pragma unroll
    for (int i = 0; i < 8; i++) {
        __half2 h0 = __floats2half2_rn(xv[i].x, xv[i].y);
        __half2 h1 = __floats2half2_rn(xv[i].z, xv[i].w);
        *(__half2*)(xh + (lane + 32 * i) * 4)     = h0;
        *(__half2*)(xh + (lane + 32 * i) * 4 + 2) = h1;
    }

    float logit[NEXP];
#pragma unroll
    for (int e = 0; e < NEXP; e++) {
        float acc = 0.f;
#pragma unroll
        for (int i = 0; i < 8; i++) {
            float4 g = sgw[e * 256 + lane + 32 * i];
            acc += xv[i].x * g.x + xv[i].y * g.y + xv[i].z * g.z + xv[i].w * g.w;
        }
#pragma unroll
        for (int s = 16; s > 0; s >>= 1) acc += __shfl_xor_sync(0xFFFFFFFFu, acc, s);
        logit[e] = acc;
    }

    if (lane == 0) {
        float sc[NEXP];
#pragma unroll
        for (int e = 0; e < NEXP; e++)
            sc[e] = 1.f / (1.f + __expf(-(logit[e] + sbias[e])));
        int i0 = 0;
#pragma unroll
        for (int e = 1; e < NEXP; e++) if (sc[e] > sc[i0]) i0 = e;
        int i1 = (i0 == 0) ? 1 : 0;
#pragma unroll
        for (int e = 0; e < NEXP; e++)
            if (e != i0 && sc[e] > sc[i1]) i1 = e;

        float s0 = sc[i0], s1 = sc[i1];
        float inv = 1.f / (s0 + s1 + 1e-6f);

        int slot0 = atomicAdd(&g_counts[i0], 1);
        g_perm[i0 * NTOK + slot0] = t;
        int slot1 = atomicAdd(&g_counts[i1], 1);
        g_perm[i1 * NTOK + slot1] = t;

        g_te[2 * t] = i0;     g_tl[2 * t] = slot0;     g_tw[2 * t] = s0 * inv;
        g_te[2 * t + 1] = i1; g_tl[2 * t + 1] = slot1; g_tw[2 * t + 1] = s1 * inv;
    }
}

// ---------------- 2) offsets ----------------
__global__ void offsets_kernel() {
    if (threadIdx.x == 0) {
        int s = 0;
        for (int e = 0; e < NEXP; e++) { g_offsets[e] = s; s += g_counts[e]; }
    }
}

// ---------------- 3) fp16 mma.sync grouped GEMM ----------------
// C[128,256] = A[128,K] @ B[256,K]^T per expert tile.
// 8 warps as 2(m) x 4(n); warp tile 64x64; 3-stage cp.async pipeline.
template <int KTOT, int NTOTAL, bool IS_G1>
__global__ void __launch_bounds__(256, 1) gemm_mma(const __half* __restrict__ Ah,
                                                   const __half* __restrict__ Wh) {
    int e = blockIdx.z;
    int cnt = g_counts[e];
    int m0 = blockIdx.y * MT;
    if (m0 >= cnt) return;
    int n0 = blockIdx.x * NT;
    int off = g_offsets[e];

    extern __shared__ char smem[];
    uint32_t sb = smem_u32(smem);
    int tid = threadIdx.x, wid = tid >> 5, lane = tid & 31;

    // ---- staging: A rows (2 threads/row, 4 chunks each); B row = tid, 8 chunks
    int ra = tid & 127;
    int ha = tid >> 7;
    bool avalid = (m0 + ra) < cnt;
    const __half* asrc;
    if (IS_G1) {
        int tok = avalid ? g_perm[e * NTOK + m0 + ra] : 0;
        asrc = Ah + (size_t)tok * KTOT + ha * 32;
    } else {
        asrc = Ah + (size_t)(avalid ? (off + m0 + ra) : 0) * KTOT + ha * 32;
    }
    const __half* bsrc = Wh + (size_t)e * NTOTAL * KTOT + (size_t)(n0 + tid) * KTOT;
    uint32_t adst0 = sb + (uint32_t)ra * 128;
    uint32_t bdst0 = sb + SB_BASE + (uint32_t)tid * 128;
    uint32_t asz = avalid ? 16u : 0u;
    uint32_t rxa = (uint32_t)(ra & 7);
    uint32_t rxb = (uint32_t)(tid & 7);

    auto issue = [&](int kc, int st) {
        uint32_t ab = adst0 + st * SA_ST;
        const __half* as = asrc + kc * BK;
#pragma unroll
        for (int j = 0; j < 4; j++) {
            uint32_t ch = (uint32_t)(ha * 4 + j);
            CPASYNC16(ab + ((ch ^ rxa) << 4), as + j * 8, asz);
        }
        uint32_t bb = bdst0 + st * SB_ST;
        const __half* bs = bsrc + kc * BK;
#pragma unroll
        for (int j = 0; j < 8; j++)
            CPASYNC16(bb + (((uint32_t)j ^ rxb) << 4), bs + j * 8, 16u);
        CPCOMMIT();
    };

    // ---- fragment geometry: warp tile 64(m) x 64(n)
    int wm = wid >> 2, wn = wid & 3;
    int m_base = wm * 64, n_base = wn * 64;
    int lr8 = lane & 7, q = lane >> 3;

    int rowA[4], rowB[4];
#pragma unroll
    for (int mi = 0; mi < 4; mi++) rowA[mi] = m_base + mi * 16 + (q & 1) * 8 + lr8;
#pragma unroll
    for (int np = 0; np < 4; np++) rowB[np] = n_base + np * 16 + (q >> 1) * 8 + lr8;

    float acc[4][8][4];
#pragma unroll
    for (int mi = 0; mi < 4; mi++)
#pragma unroll
        for (int nj = 0; nj < 8; nj++)
#pragma unroll
            for (int c = 0; c < 4; c++) acc[mi][nj][c] = 0.f;

    constexpr int NC = KTOT / BK;
    issue(0, 0);
    issue(1, 1);

    for (int kc = 0; kc < NC; kc++) {
        int st = kc % 3;
        if (kc + 2 < NC) {
            issue(kc + 2, (kc + 2) % 3);
            asm volatile("cp.async.wait_group 2;" ::: "memory");
        } else if (kc + 1 < NC) {
            asm volatile("cp.async.wait_group 1;" ::: "memory");
        } else {
            asm volatile("cp.async.wait_group 0;" ::: "memory");
        }
        __syncthreads();

        uint32_t Ab = sb + st * SA_ST;
        uint32_t Bb = sb + SB_BASE + st * SB_ST;
#pragma unroll
        for (int s = 0; s < 4; s++) {
            uint32_t a[4][4];
#pragma unroll
            for (int mi = 0; mi < 4; mi++) {
                uint32_t ch = (uint32_t)(s * 2 + (q >> 1));
                uint32_t ad = Ab + (uint32_t)rowA[mi] * 128 + ((ch ^ (uint32_t)(rowA[mi] & 7)) << 4);
                LDSM_X4(a[mi][0], a[mi][1], a[mi][2], a[mi][3], ad);
            }
#pragma unroll
            for (int np = 0; np < 4; np++) {
                uint32_t b0, b1, b2, b3;
                uint32_t ch = (uint32_t)(s * 2 + (q & 1));
                uint32_t bd = Bb + (uint32_t)rowB[np] * 128 + ((ch ^ (uint32_t)(rowB[np] & 7)) << 4);
                LDSM_X4(b0, b1, b2, b3, bd);
#pragma unroll
                for (int mi = 0; mi < 4; mi++) {
                    MMA16816(acc[mi][2 * np],     a[mi], b0, b1);
                    MMA16816(acc[mi][2 * np + 1], a[mi], b2, b3);
                }
            }
        }
        __syncthreads();
    }

    // ---- epilogue
    int g = lane >> 2, t2 = (lane & 3) * 2;
#pragma unroll
    for (int mi = 0; mi < 4; mi++) {
        int r0 = m_base + mi * 16 + g;
        int r1 = r0 + 8;
        bool v0 = (m0 + r0) < cnt;
        bool v1 = (m0 + r1) < cnt;
        size_t gr0 = (size_t)(off + m0 + r0);
        size_t gr1 = (size_t)(off + m0 + r1);
#pragma unroll
        for (int nj = 0; nj < 8; nj++) {
            int col = n0 + n_base + nj * 8 + t2;
            if (IS_G1) {
                if (v0)
                    *(__half2*)(g_hh + gr0 * NTOTAL + col) =
                        __floats2half2_rn(silu(acc[mi][nj][0]), silu(acc[mi][nj][1]));
                if (v1)
                    *(__half2*)(g_hh + gr1 * NTOTAL + col) =
                        __floats2half2_rn(silu(acc[mi][nj][2]), silu(acc[mi][nj][3]));
            } else {
                if (v0)
                    *(float2*)(g_y + gr0 * NTOTAL + col) =
                        make_float2(acc[mi][nj][0], acc[mi][nj][1]);
                if (v1)
                    *(float2*)(g_y + gr1 * NTOTAL + col) =
                        make_float2(acc[mi][nj][2], acc[mi][nj][3]);
            }
        }
    }
}

// ---------------- 4) combine ----------------
__global__ void combine_kernel(float* __restrict__ out) {
    int i = blockIdx.x * blockDim.x + threadIdx.x;   // over NTOK*256 float4s
    int t = i >> 8;
    int c = i & 255;
    int s0 = g_offsets[g_te[2 * t]] + g_tl[2 * t];
    int s1 = g_offsets[g_te[2 * t + 1]] + g_tl[2 * t + 1];
    float w0 = g_tw[2 * t], w1 = g_tw[2 * t + 1];
    const float4* y = (const float4*)g_y;
    float4 a = y[(size_t)s0 * 256 + c];
    float4 b = y[(size_t)s1 * 256 + c];
    float4 o;
    o.x = w0 * a.x + w1 * b.x;
    o.y = w0 * a.y + w1 * b.y;
    o.z = w0 * a.z + w1 * b.z;
    o.w = w0 * a.w + w1 * b.w;
    ((float4*)out)[i] = o;
}

// ---------------- launch ----------------
extern "C" void kernel_launch(void* const* d_in, const int* in_sizes, int n_in,
                              void* d_out, int out_size) {
    const float* x      = (const float*)d_in[0];
    const float* gate_w = (const float*)d_in[1];
    const float* bias   = (const float*)d_in[2];
    const float* w1     = (const float*)d_in[3];
    const float* w2     = (const float*)d_in[4];
    float* out          = (float*)d_out;

    cudaFuncSetAttribute(gemm_mma<DIMV, HDIM, true>,
                         cudaFuncAttributeMaxDynamicSharedMemorySize, SMEM_BYTES);
    cudaFuncSetAttribute(gemm_mma<HDIM, DIMV, false>,
                         cudaFuncAttributeMaxDynamicSharedMemorySize, SMEM_BYTES);

    zero_kernel<<<1, 32>>>();

    int n4w = (NEXP * HDIM * DIMV) / 4;   // 4,194,304
    __half* w1h; cudaGetSymbolAddress((void**)&w1h, g_w1h);
    __half* w2h; cudaGetSymbolAddress((void**)&w2h, g_w2h);
    cvt_kernel<<<n4w / 256, 256>>>((const float4*)w1, (__half2*)w1h, n4w);
    cvt_kernel<<<n4w / 256, 256>>>((const float4*)w2, (__half2*)w2h, n4w);

    gate_kernel<<<NTOK / 8, 256>>>(x, gate_w, bias);
    offsets_kernel<<<1, 32>>>();

    __half* xh; cudaGetSymbolAddress((void**)&xh, g_xh);
    __half* hh; cudaGetSymbolAddress((void**)&hh, g_hh);

    gemm_mma<DIMV, HDIM, true><<<dim3(HDIM / NT, NTOK / MT, NEXP), 256, SMEM_BYTES>>>(xh, w1h);
    gemm_mma<HDIM, DIMV, false><<<dim3(DIMV / NT, NTOK / MT, NEXP), 256, SMEM_BYTES>>>(hh, w2h);

    combine_kernel<<<(NTOK * 256) / 256, 256>>>(out);
}

// round 6
// speedup vs baseline: 6.6783x; 1.2431x over previous
#include <cuda_runtime.h>
#include <cuda_fp16.h>
#include <math.h>
#include <stdint.h>

#define NTOK 2048
#define DIMV 1024
#define NEXP 8
#define HDIM 2048

#define MT 128
#define NT 256
#define BK 64              // halves per K chunk = 128 bytes per row

// smem: 3 stages of (A: 128*128B = 16KB) + (B: 256*128B = 32KB)
#define SA_ST 16384
#define SB_BASE 49152
#define SB_ST 32768
#define SMEM_BYTES (SB_BASE + 3 * SB_ST)   // 147456

// ---------------- scratch ----------------
__device__ int   g_counts[NEXP];
__device__ int   g_offsets[NEXP];
__device__ int   g_perm[NEXP * NTOK];
__device__ float g_pw[NEXP * NTOK];
__device__ __align__(16) __half g_xh[NTOK * DIMV];
__device__ __align__(16) __half g_w1h[(size_t)NEXP * HDIM * DIMV];
__device__ __align__(16) __half g_w2h[(size_t)NEXP * DIMV * HDIM];
__device__ __align__(16) __half g_hh[(size_t)2 * NTOK * HDIM];

// ---------------- PTX helpers ----------------
__device__ __forceinline__ uint32_t smem_u32(const void* p) {
    uint32_t a;
    asm("{ .reg .u64 t; cvta.to.shared.u64 t, %1; cvt.u32.u64 %0, t; }" : "=r"(a) : "l"(p));
    return a;
}
#define CPASYNC16(dst, src, sz) \
    asm volatile("cp.async.cg.shared.global [%0], [%1], 16, %2;" :: "r"(dst), "l"(src), "r"(sz) : "memory")
#define CPCOMMIT() asm volatile("cp.async.commit_group;" ::: "memory")

#define LDSM_X4(r0, r1, r2, r3, addr) \
    asm volatile("ldmatrix.sync.aligned.m8n8.x4.shared.b16 {%0,%1,%2,%3}, [%4];" \
        : "=r"(r0), "=r"(r1), "=r"(r2), "=r"(r3) : "r"(addr))

#define MMA16816(d, a, b0, b1) \
    asm volatile("mma.sync.aligned.m16n8k16.row.col.f32.f16.f16.f32 " \
        "{%0,%1,%2,%3},{%4,%5,%6,%7},{%8,%9},{%0,%1,%2,%3};" \
        : "+f"((d)[0]), "+f"((d)[1]), "+f"((d)[2]), "+f"((d)[3]) \
        : "r"((a)[0]), "r"((a)[1]), "r"((a)[2]), "r"((a)[3]), "r"(b0), "r"(b1))

__device__ __forceinline__ float silu(float v) { return v / (1.f + __expf(-v)); }

// ---------------- 0) zero counters ----------------
__global__ void zero_kernel() {
    if (threadIdx.x < NEXP) g_counts[threadIdx.x] = 0;
}

// ---------------- 1) fused prep: cvt(w1), cvt(w2), zero(out), gate ----------------
// grid roles: [0,16384) w1 cvt | [16384,32768) w2 cvt | [32768,34816) zero out |
//             [34816,35072) gate (8 tokens per block, warp per token)
#define NB_W (NEXP * HDIM * DIMV / 4 / 256)    // 16384 blocks per weight tensor
#define NB_Z (NTOK * DIMV / 4 / 256)           // 2048
#define NB_G (NTOK / 8)                        // 256

__global__ void __launch_bounds__(256) prep_kernel(const float4* __restrict__ w1,
                                                   const float4* __restrict__ w2,
                                                   const float*  __restrict__ x,
                                                   const float*  __restrict__ gw,
                                                   const float*  __restrict__ bias,
                                                   float4* __restrict__ out4) {
    int b = blockIdx.x;
    int tid = threadIdx.x;

    if (b < 2 * NB_W) {
        const float4* src = (b < NB_W) ? w1 : w2;
        __half2* dst = (__half2*)((b < NB_W) ? g_w1h : g_w2h);
        int i = (b % NB_W) * 256 + tid;
        float4 v = src[i];
        dst[2 * i]     = __floats2half2_rn(v.x, v.y);
        dst[2 * i + 1] = __floats2half2_rn(v.z, v.w);
        return;
    }
    if (b < 2 * NB_W + NB_Z) {
        int i = (b - 2 * NB_W) * 256 + tid;
        out4[i] = make_float4(0.f, 0.f, 0.f, 0.f);
        return;
    }

    // ---- gate role: warp per token
    int wid = tid >> 5, lane = tid & 31;
    int t = (b - 2 * NB_W - NB_Z) * 8 + wid;

    const float4* xr = (const float4*)(x + (size_t)t * DIMV);
    float4 xv[8];
#pragma unroll
    for (int i = 0; i < 8; i++) xv[i] = xr[lane + 32 * i];

    __half* xh = g_xh + (size_t)t * DIMV;
#pragma unroll
    for (int i = 0; i < 8; i++) {
        *(__half2*)(xh + (lane + 32 * i) * 4)     = __floats2half2_rn(xv[i].x, xv[i].y);
        *(__half2*)(xh + (lane + 32 * i) * 4 + 2) = __floats2half2_rn(xv[i].z, xv[i].w);
    }

    const float4* g4 = (const float4*)gw;
    float logit[NEXP];
#pragma unroll
    for (int e = 0; e < NEXP; e++) {
        float acc = 0.f;
#pragma unroll
        for (int i = 0; i < 8; i++) {
            float4 g = __ldg(&g4[e * 256 + lane + 32 * i]);
            acc += xv[i].x * g.x + xv[i].y * g.y + xv[i].z * g.z + xv[i].w * g.w;
        }
#pragma unroll
        for (int s = 16; s > 0; s >>= 1) acc += __shfl_xor_sync(0xFFFFFFFFu, acc, s);
        logit[e] = acc;
    }

    if (lane == 0) {
        float sc[NEXP];
#pragma unroll
        for (int e = 0; e < NEXP; e++)
            sc[e] = 1.f / (1.f + __expf(-(logit[e] + bias[e])));
        int i0 = 0;
#pragma unroll
        for (int e = 1; e < NEXP; e++) if (sc[e] > sc[i0]) i0 = e;
        int i1 = (i0 == 0) ? 1 : 0;
#pragma unroll
        for (int e = 0; e < NEXP; e++)
            if (e != i0 && sc[e] > sc[i1]) i1 = e;

        float s0 = sc[i0], s1 = sc[i1];
        float inv = 1.f / (s0 + s1 + 1e-6f);

        int slot0 = atomicAdd(&g_counts[i0], 1);
        g_perm[i0 * NTOK + slot0] = t;
        g_pw[i0 * NTOK + slot0]   = s0 * inv;
        int slot1 = atomicAdd(&g_counts[i1], 1);
        g_perm[i1 * NTOK + slot1] = t;
        g_pw[i1 * NTOK + slot1]   = s1 * inv;
    }
}

// ---------------- 2) offsets ----------------
__global__ void offsets_kernel() {
    if (threadIdx.x == 0) {
        int s = 0;
        for (int e = 0; e < NEXP; e++) { g_offsets[e] = s; s += g_counts[e]; }
    }
}

// ---------------- 3) fp16 mma.sync grouped GEMM, 512 threads ----------------
// C[128,256] = A[128,K] @ B[256,K]^T per expert tile.
// 16 warps as 4(m) x 4(n); warp tile 32x64; 3-stage cp.async, one sync/chunk.
template <int KTOT, int NTOTAL, bool IS_G1>
__global__ void __launch_bounds__(512, 1) gemm_mma(const __half* __restrict__ Ah,
                                                   const __half* __restrict__ Wh,
                                                   float* __restrict__ out) {
    int e = blockIdx.z;
    int cnt = g_counts[e];
    int m0 = blockIdx.y * MT;
    if (m0 >= cnt) return;
    int n0 = blockIdx.x * NT;
    int off = g_offsets[e];

    extern __shared__ char smem[];
    uint32_t sb = smem_u32(smem);
    int tid = threadIdx.x, wid = tid >> 5, lane = tid & 31;

    // ---- staging: A row = tid>>2 (4 thr/row, 2 x 16B each); B row = tid>>1 (2 thr/row, 4 x 16B)
    int ra = tid >> 2, qa = tid & 3;
    int rb = tid >> 1, qb = tid & 1;
    bool avalid = (m0 + ra) < cnt;
    const __half* asrc;
    if (IS_G1) {
        int tok = avalid ? g_perm[e * NTOK + m0 + ra] : 0;
        asrc = Ah + (size_t)tok * KTOT + qa * 16;
    } else {
        asrc = Ah + (size_t)(avalid ? (off + m0 + ra) : 0) * KTOT + qa * 16;
    }
    const __half* bsrc = Wh + (size_t)e * NTOTAL * KTOT + (size_t)(n0 + rb) * KTOT + qb * 32;
    uint32_t adst0 = sb + (uint32_t)ra * 128;
    uint32_t bdst0 = sb + SB_BASE + (uint32_t)rb * 128;
    uint32_t asz = avalid ? 16u : 0u;
    uint32_t rxa = (uint32_t)(ra & 7);
    uint32_t rxb = (uint32_t)(rb & 7);

    auto issue = [&](int kc, int st) {
        uint32_t ab = adst0 + st * SA_ST;
        const __half* as = asrc + kc * BK;
#pragma unroll
        for (int j = 0; j < 2; j++) {
            uint32_t ch = (uint32_t)(qa * 2 + j);
            CPASYNC16(ab + ((ch ^ rxa) << 4), as + j * 8, asz);
        }
        uint32_t bb = bdst0 + st * SB_ST;
        const __half* bs = bsrc + kc * BK;
#pragma unroll
        for (int j = 0; j < 4; j++) {
            uint32_t ch = (uint32_t)(qb * 4 + j);
            CPASYNC16(bb + ((ch ^ rxb) << 4), bs + j * 8, 16u);
        }
        CPCOMMIT();
    };

    // ---- fragment geometry: warp tile 32(m) x 64(n), warps 4m x 4n
    int wm = wid >> 2, wn = wid & 3;
    int m_base = wm * 32, n_base = wn * 64;
    int lr8 = lane & 7, q = lane >> 3;

    int rowA[2], rowB[4];
#pragma unroll
    for (int mi = 0; mi < 2; mi++) rowA[mi] = m_base + mi * 16 + (q & 1) * 8 + lr8;
#pragma unroll
    for (int np = 0; np < 4; np++) rowB[np] = n_base + np * 16 + (q >> 1) * 8 + lr8;

    float acc[2][8][4];
#pragma unroll
    for (int mi = 0; mi < 2; mi++)
#pragma unroll
        for (int nj = 0; nj < 8; nj++)
#pragma unroll
            for (int c = 0; c < 4; c++) acc[mi][nj][c] = 0.f;

    constexpr int NC = KTOT / BK;
    issue(0, 0);
    issue(1, 1);

    for (int kc = 0; kc < NC; kc++) {
        int st = kc % 3;
        if (kc + 1 < NC) {
            asm volatile("cp.async.wait_group 1;" ::: "memory");
        } else {
            asm volatile("cp.async.wait_group 0;" ::: "memory");
        }
        __syncthreads();
        if (kc + 2 < NC) issue(kc + 2, (kc + 2) % 3);

        uint32_t Ab = sb + st * SA_ST;
        uint32_t Bb = sb + SB_BASE + st * SB_ST;
#pragma unroll
        for (int s = 0; s < 4; s++) {
            uint32_t a[2][4];
#pragma unroll
            for (int mi = 0; mi < 2; mi++) {
                uint32_t ch = (uint32_t)(s * 2 + (q >> 1));
                uint32_t ad = Ab + (uint32_t)rowA[mi] * 128 + ((ch ^ (uint32_t)(rowA[mi] & 7)) << 4);
                LDSM_X4(a[mi][0], a[mi][1], a[mi][2], a[mi][3], ad);
            }
#pragma unroll
            for (int np = 0; np < 4; np++) {
                uint32_t b0, b1, b2, b3;
                uint32_t ch = (uint32_t)(s * 2 + (q & 1));
                uint32_t bd = Bb + (uint32_t)rowB[np] * 128 + ((ch ^ (uint32_t)(rowB[np] & 7)) << 4);
                LDSM_X4(b0, b1, b2, b3, bd);
#pragma unroll
                for (int mi = 0; mi < 2; mi++) {
                    MMA16816(acc[mi][2 * np],     a[mi], b0, b1);
                    MMA16816(acc[mi][2 * np + 1], a[mi], b2, b3);
                }
            }
        }
    }

    // ---- epilogue
    int g = lane >> 2, t2 = (lane & 3) * 2;
#pragma unroll
    for (int mi = 0; mi < 2; mi++) {
        int r0 = m_base + mi * 16 + g;
        int r1 = r0 + 8;
        bool v0 = (m0 + r0) < cnt;
        bool v1 = (m0 + r1) < cnt;
        if (IS_G1) {
            size_t gr0 = (size_t)(off + m0 + r0);
            size_t gr1 = (size_t)(off + m0 + r1);
#pragma unroll
            for (int nj = 0; nj < 8; nj++) {
                int col = n0 + n_base + nj * 8 + t2;
                if (v0)
                    *(__half2*)(g_hh + gr0 * NTOTAL + col) =
                        __floats2half2_rn(silu(acc[mi][nj][0]), silu(acc[mi][nj][1]));
                if (v1)
                    *(__half2*)(g_hh + gr1 * NTOTAL + col) =
                        __floats2half2_rn(silu(acc[mi][nj][2]), silu(acc[mi][nj][3]));
            }
        } else {
            int tok0 = 0, tok1 = 0;
            float wt0 = 0.f, wt1 = 0.f;
            if (v0) { tok0 = g_perm[e * NTOK + m0 + r0]; wt0 = g_pw[e * NTOK + m0 + r0]; }
            if (v1) { tok1 = g_perm[e * NTOK + m0 + r1]; wt1 = g_pw[e * NTOK + m0 + r1]; }
#pragma unroll
            for (int nj = 0; nj < 8; nj++) {
                int col = n0 + n_base + nj * 8 + t2;
                if (v0) {
                    float* o = out + (size_t)tok0 * DIMV + col;
                    atomicAdd(o,     wt0 * acc[mi][nj][0]);
                    atomicAdd(o + 1, wt0 * acc[mi][nj][1]);
                }
                if (v1) {
                    float* o = out + (size_t)tok1 * DIMV + col;
                    atomicAdd(o,     wt1 * acc[mi][nj][2]);
                    atomicAdd(o + 1, wt1 * acc[mi][nj][3]);
                }
            }
        }
    }
}

// ---------------- launch ----------------
extern "C" void kernel_launch(void* const* d_in, const int* in_sizes, int n_in,
                              void* d_out, int out_size) {
    const float* x      = (const float*)d_in[0];
    const float* gate_w = (const float*)d_in[1];
    const float* bias   = (const float*)d_in[2];
    const float* w1     = (const float*)d_in[3];
    const float* w2     = (const float*)d_in[4];
    float* out          = (float*)d_out;

    cudaFuncSetAttribute(gemm_mma<DIMV, HDIM, true>,
                         cudaFuncAttributeMaxDynamicSharedMemorySize, SMEM_BYTES);
    cudaFuncSetAttribute(gemm_mma<HDIM, DIMV, false>,
                         cudaFuncAttributeMaxDynamicSharedMemorySize, SMEM_BYTES);

    zero_kernel<<<1, 32>>>();
    prep_kernel<<<2 * NB_W + NB_Z + NB_G, 256>>>((const float4*)w1, (const float4*)w2,
                                                 x, gate_w, bias, (float4*)out);
    offsets_kernel<<<1, 32>>>();

    __half* xh;  cudaGetSymbolAddress((void**)&xh, g_xh);
    __half* hh;  cudaGetSymbolAddress((void**)&hh, g_hh);
    __half* w1h; cudaGetSymbolAddress((void**)&w1h, g_w1h);
    __half* w2h; cudaGetSymbolAddress((void**)&w2h, g_w2h);

    gemm_mma<DIMV, HDIM, true><<<dim3(HDIM / NT, NTOK / MT, NEXP), 512, SMEM_BYTES>>>(xh, w1h, nullptr);
    gemm_mma<HDIM, DIMV, false><<<dim3(DIMV / NT, NTOK / MT, NEXP), 512, SMEM_BYTES>>>(hh, w2h, out);
}